// round 11
// baseline (speedup 1.0000x reference)
#include <cuda_runtime.h>
#include <cuda_bf16.h>
#include <math.h>
#include <stdint.h>

#define NB 4
#define NC 256
#define NH 128
#define NW 128
#define NHW (NH*NW)
#define NINNER 256
#define NHEADS 4
#define NDH 64
#define NS 16
#define NSS 256
#define GK 256

// -------- scratch --------
__device__ float g_t1t[NB*NHW*NC];
__device__ float g_qkv[NB*3*NINNER*NHW];
__device__ float g_kp [NB*NINNER*NSS];
__device__ float g_vp [NB*NINNER*NSS];
__device__ float g_av [NB*NINNER*NHW];
__device__ float g_t2t[NB*NHW*NINNER];

// ---- bf16x3 helpers ----
__device__ __forceinline__ void splitpack(float x0, float x1, uint32_t& b, uint32_t& s) {
  __nv_bfloat162 hb = __floats2bfloat162_rn(x0, x1);
  uint32_t bb = *(uint32_t*)&hb;
  float b0 = __uint_as_float(bb << 16);
  float b1 = __uint_as_float(bb & 0xffff0000u);
  __nv_bfloat162 hs = __floats2bfloat162_rn(x0 - b0, x1 - b1);
  b = bb;
  s = *(uint32_t*)&hs;
}
__device__ __forceinline__ void mma16(float* c, const uint32_t* a, const uint32_t* b) {
  asm volatile("mma.sync.aligned.m16n8k16.row.col.f32.bf16.bf16.f32 "
    "{%0,%1,%2,%3}, {%4,%5,%6,%7}, {%8,%9}, {%0,%1,%2,%3};"
    : "+f"(c[0]), "+f"(c[1]), "+f"(c[2]), "+f"(c[3])
    : "r"(a[0]), "r"(a[1]), "r"(a[2]), "r"(a[3]), "r"(b[0]), "r"(b[1]));
}

// ============== fused depthwise 3x3 (pad 1) + transpose ==============
__global__ void __launch_bounds__(256) dw_t(const float* __restrict__ in,
                                            const float* __restrict__ wt,
                                            float* __restrict__ out) {
  __shared__ float t[32][33];
  int hw0 = blockIdx.x*32, c0 = blockIdx.y*32, b = blockIdx.z;
  int tx = threadIdx.x & 31, ty = threadIdx.x >> 5;
  int x = (hw0 + tx) & (NW-1), y = (hw0 + tx) >> 7;
  #pragma unroll
  for (int r = 0; r < 4; r++) {
    int c = c0 + ty + r*8;
    const float* wp = wt + c*9;
    const float* ip = in + ((size_t)b*256 + c)*NHW;
    float s = 0.f;
    #pragma unroll
    for (int dy = -1; dy <= 1; dy++) {
      int yy = y + dy;
      if ((unsigned)yy >= NH) continue;
      #pragma unroll
      for (int dx = -1; dx <= 1; dx++) {
        int xx = x + dx;
        if ((unsigned)xx >= NW) continue;
        s = fmaf(ip[yy*NW+xx], wp[(dy+1)*3 + dx+1], s);
      }
    }
    t[ty + r*8][tx] = s;
  }
  __syncthreads();
  #pragma unroll
  for (int r = 0; r < 4; r++) {
    int hw = hw0 + ty + r*8;
    out[((size_t)b*NHW + hw)*256 + c0 + tx] = t[tx][ty + r*8];
  }
}

// ======================= bf16x3 mma.sync GEMM =======================
#define GP 20
__global__ void __launch_bounds__(256, 2) mm_bf16(const float* __restrict__ A,
                                                  const float* __restrict__ Bt,
                                                  float* __restrict__ C, int M) {
  __shared__ uint32_t sh[4*128*GP];
  uint32_t* sAb = sh;
  uint32_t* sAs = sh + 2560;
  uint32_t* sBb = sh + 5120;
  uint32_t* sBs = sh + 7680;

  const int tid = threadIdx.x;
  const int wid = tid >> 5, lane = tid & 31;
  const int wm = wid >> 2, wn = wid & 3;
  const int g = lane >> 2, tg = lane & 3;
  const int n0 = blockIdx.x * 128;
  const int m0 = blockIdx.y * 128;
  const int bz = blockIdx.z;

  const float* Arow = A + (size_t)m0*GK;
  const float* Brow = Bt + ((size_t)bz*NHW + n0)*GK;

  float acc[4][4][4];
  #pragma unroll
  for (int i=0;i<4;i++)
    #pragma unroll
    for (int j=0;j<4;j++)
      #pragma unroll
      for (int l=0;l<4;l++) acc[i][j][l] = 0.f;

  for (int kc = 0; kc < GK; kc += 32) {
    #pragma unroll
    for (int i = 0; i < 4; i++) {
      int e = i*256 + tid; int r = e >> 3, c4 = e & 7;
      float4 v = *(const float4*)(Arow + (size_t)r*GK + kc + c4*4);
      uint32_t b0, s0, b1, s1;
      splitpack(v.x, v.y, b0, s0);
      splitpack(v.z, v.w, b1, s1);
      *(uint2*)&sAb[r*GP + c4*2] = make_uint2(b0, b1);
      *(uint2*)&sAs[r*GP + c4*2] = make_uint2(s0, s1);
      float4 w = *(const float4*)(Brow + (size_t)r*GK + kc + c4*4);
      splitpack(w.x, w.y, b0, s0);
      splitpack(w.z, w.w, b1, s1);
      *(uint2*)&sBb[r*GP + c4*2] = make_uint2(b0, b1);
      *(uint2*)&sBs[r*GP + c4*2] = make_uint2(s0, s1);
    }
    __syncthreads();
    #pragma unroll
    for (int ks = 0; ks < 2; ks++) {
      int k0 = ks*8;
      uint32_t bb[4][2], bs[4][2];
      #pragma unroll
      for (int nt = 0; nt < 4; nt++) {
        int n = wn*32 + nt*8 + g;
        bb[nt][0] = sBb[n*GP + k0 + tg];
        bb[nt][1] = sBb[n*GP + k0 + tg + 4];
        bs[nt][0] = sBs[n*GP + k0 + tg];
        bs[nt][1] = sBs[n*GP + k0 + tg + 4];
      }
      #pragma unroll
      for (int mt = 0; mt < 4; mt++) {
        int m = wm*64 + mt*16 + g;
        uint32_t ab[4], as_[4];
        ab[0]  = sAb[m*GP + k0 + tg];
        ab[1]  = sAb[(m+8)*GP + k0 + tg];
        ab[2]  = sAb[m*GP + k0 + tg + 4];
        ab[3]  = sAb[(m+8)*GP + k0 + tg + 4];
        as_[0] = sAs[m*GP + k0 + tg];
        as_[1] = sAs[(m+8)*GP + k0 + tg];
        as_[2] = sAs[m*GP + k0 + tg + 4];
        as_[3] = sAs[(m+8)*GP + k0 + tg + 4];
        #pragma unroll
        for (int nt = 0; nt < 4; nt++) {
          mma16(acc[mt][nt], ab,  bb[nt]);
          mma16(acc[mt][nt], ab,  bs[nt]);
          mma16(acc[mt][nt], as_, bb[nt]);
        }
      }
    }
    __syncthreads();
  }

  float* Cb = C + (size_t)bz*M*NHW;
  #pragma unroll
  for (int mt = 0; mt < 4; mt++) {
    int row = m0 + wm*64 + mt*16 + g;
    #pragma unroll
    for (int nt = 0; nt < 4; nt++) {
      int col = n0 + wn*32 + nt*8 + 2*tg;
      *(float2*)(Cb + (size_t)row*NHW + col) =
          make_float2(acc[mt][nt][0], acc[mt][nt][1]);
      *(float2*)(Cb + (size_t)(row+8)*NHW + col) =
          make_float2(acc[mt][nt][2], acc[mt][nt][3]);
    }
  }
}

// ======================= 8x8 max pool =======================
__global__ void pool8(const float* __restrict__ qkv, float* __restrict__ kp,
                      float* __restrict__ vp) {
  int idx = blockIdx.x*256 + threadIdx.x;
  int which = idx >> 18;
  int r = idx & 262143;
  int ow = r & 15, oh = (r >> 4) & 15;
  int c = (r >> 8) & 255;
  int b = r >> 16;
  const float* ip = qkv + ((size_t)(b*768 + (which ? 512 : 256) + c))*NHW
                    + (oh*8)*NW + ow*8;
  float m = -1e30f;
  #pragma unroll
  for (int i=0;i<8;i++)
    #pragma unroll
    for (int j=0;j<8;j++)
      m = fmaxf(m, ip[i*NW+j]);
  if (which) vp[r] = m; else kp[r] = m;
}

// ======================= fused bf16x3 attention, QT=32, 2 CTAs/SM =======================
#define SSTR 264
#define KPP 36
#define QPP 36
#define RPP 36
#define PPP 132
#define VPP 68
#define LSTR 68
#define OSTR 66

__global__ void __launch_bounds__(256, 2) attn_k(
    const float* __restrict__ qkv, const float* __restrict__ kp,
    const float* __restrict__ vp, const float* __restrict__ relw,
    const float* __restrict__ relh, float* __restrict__ attn_out,
    float* __restrict__ av) {
  extern __shared__ float smf[];
  uint32_t* smu = (uint32_t*)smf;
  float*    sS  = smf;                    // 8448
  uint32_t* sKb = smu + 8448;             // 4608
  uint32_t* sKs = smu + 13056;            // 4608
  uint32_t* sQb = smu + 17664;            // 1152
  uint32_t* sQs = smu + 18816;            // 1152
  uint32_t* sRb = smu + 19968;            // 2304
  uint32_t* sRs = smu + 22272;            // 2304
  float*    sL  = smf + 24576;            // 2176
  uint32_t* sPb = sKb;                    // 4224 (overlays K)
  uint32_t* sPs = sKs;                    // 4224
  uint32_t* sVb = smu + 17664;            // 4352 (overlays Q/R)
  uint32_t* sVs = smu + 22016;            // 4352 (overlays R/L)
  float*    sO  = smf;                    // 2112 (overlays sS)

  const int tid = threadIdx.x;
  const int wid = tid >> 5, lane = tid & 31;
  const int g = lane >> 2, tg = lane & 3;
  const int head = blockIdx.y;
  const int b = blockIdx.z;
  const int i0 = blockIdx.x*32;
  const int hq = i0 >> 7;
  const int w0 = i0 & (NW-1);
  const int h8 = hq >> 3;
  const int wm = wid >> 2, wn = wid & 3;

  // ---- load Q (32 q x 32 dp), split+pack ----
  #pragma unroll
  for (int l = 0; l < 4; l++) {
    int e = l*256 + tid;
    int dp = e >> 5, qi = e & 31;
    float x0 = qkv[((size_t)(b*768) + (2*dp)*NHEADS + head)*NHW + i0 + qi];
    float x1 = qkv[((size_t)(b*768) + (2*dp+1)*NHEADS + head)*NHW + i0 + qi];
    splitpack(x0, x1, sQb[qi*QPP + dp], sQs[qi*QPP + dp]);
  }
  // ---- rel tables padded to 64 rows: 0..30 relh, 32..62 relw ----
  #pragma unroll
  for (int l = 0; l < 8; l++) {
    int e = l*256 + tid;
    int dp = e >> 6, n = e & 63;
    float x0 = 0.f, x1 = 0.f;
    if (n < 31)                 { x0 = relh[n*64 + 2*dp];      x1 = relh[n*64 + 2*dp + 1]; }
    else if (n >= 32 && n < 63) { x0 = relw[(n-32)*64 + 2*dp]; x1 = relw[(n-32)*64 + 2*dp + 1]; }
    splitpack(x0, x1, sRb[n*RPP + dp], sRs[n*RPP + dp]);
  }

  // ================= QK over two key halves =================
  float accS[2][4][4];
  #pragma unroll
  for (int h2=0;h2<2;h2++)
    #pragma unroll
    for (int j=0;j<4;j++)
      #pragma unroll
      for (int l=0;l<4;l++) accS[h2][j][l]=0.f;

  #pragma unroll 1
  for (int half = 0; half < 2; half++) {
    if (half == 1) __syncthreads();    // all warps done with K half 0
    {
      int j = tid & 127, dpb = (tid >> 7)*16;
      #pragma unroll 4
      for (int dp2 = 0; dp2 < 16; dp2++) {
        int dp = dpb + dp2;
        float x0 = kp[((size_t)(b*NINNER) + (2*dp)*NHEADS + head)*NSS + half*128 + j];
        float x1 = kp[((size_t)(b*NINNER) + (2*dp+1)*NHEADS + head)*NSS + half*128 + j];
        splitpack(x0, x1, sKb[j*KPP + dp], sKs[j*KPP + dp]);
      }
    }
    __syncthreads();
    #pragma unroll
    for (int ks = 0; ks < 4; ks++) {
      int k0 = ks*8;
      uint32_t bb[4][2], bs[4][2];
      #pragma unroll
      for (int nt = 0; nt < 4; nt++) {
        int j = wn*32 + nt*8 + g;
        bb[nt][0] = sKb[j*KPP + k0 + tg];
        bb[nt][1] = sKb[j*KPP + k0 + tg + 4];
        bs[nt][0] = sKs[j*KPP + k0 + tg];
        bs[nt][1] = sKs[j*KPP + k0 + tg + 4];
      }
      int q = wm*16 + g;
      uint32_t ab[4], as_[4];
      ab[0]  = sQb[q*QPP + k0 + tg];
      ab[1]  = sQb[(q+8)*QPP + k0 + tg];
      ab[2]  = sQb[q*QPP + k0 + tg + 4];
      ab[3]  = sQb[(q+8)*QPP + k0 + tg + 4];
      as_[0] = sQs[q*QPP + k0 + tg];
      as_[1] = sQs[(q+8)*QPP + k0 + tg];
      as_[2] = sQs[q*QPP + k0 + tg + 4];
      as_[3] = sQs[(q+8)*QPP + k0 + tg + 4];
      #pragma unroll
      for (int nt = 0; nt < 4; nt++) {
        mma16(accS[half][nt], ab,  bb[nt]);
        mma16(accS[half][nt], ab,  bs[nt]);
        mma16(accS[half][nt], as_, bb[nt]);
      }
    }
  }
  // store scores
  {
    int q = wm*16 + g;
    #pragma unroll
    for (int half = 0; half < 2; half++)
      #pragma unroll
      for (int nt = 0; nt < 4; nt++) {
        int col = half*128 + wn*32 + nt*8 + 2*tg;
        *(float2*)&sS[q*SSTR + col]     = make_float2(accS[half][nt][0], accS[half][nt][1]);
        *(float2*)&sS[(q+8)*SSTR + col] = make_float2(accS[half][nt][2], accS[half][nt][3]);
      }
  }
  // ================= bias logits (32 x 64, warp = 8 cols) =================
  {
    float acc2[2][4];
    #pragma unroll
    for (int i=0;i<2;i++)
      #pragma unroll
      for (int l=0;l<4;l++) acc2[i][l]=0.f;
    #pragma unroll
    for (int ks = 0; ks < 4; ks++) {
      int k0 = ks*8;
      int n = wid*8 + g;
      uint32_t bb[2], bs[2];
      bb[0] = sRb[n*RPP + k0 + tg];
      bb[1] = sRb[n*RPP + k0 + tg + 4];
      bs[0] = sRs[n*RPP + k0 + tg];
      bs[1] = sRs[n*RPP + k0 + tg + 4];
      #pragma unroll
      for (int mt = 0; mt < 2; mt++) {
        int q = mt*16 + g;
        uint32_t ab[4], as_[4];
        ab[0]  = sQb[q*QPP + k0 + tg];
        ab[1]  = sQb[(q+8)*QPP + k0 + tg];
        ab[2]  = sQb[q*QPP + k0 + tg + 4];
        ab[3]  = sQb[(q+8)*QPP + k0 + tg + 4];
        as_[0] = sQs[q*QPP + k0 + tg];
        as_[1] = sQs[(q+8)*QPP + k0 + tg];
        as_[2] = sQs[q*QPP + k0 + tg + 4];
        as_[3] = sQs[(q+8)*QPP + k0 + tg + 4];
        mma16(acc2[mt], ab,  bb);
        mma16(acc2[mt], ab,  bs);
        mma16(acc2[mt], as_, bb);
      }
    }
    #pragma unroll
    for (int mt = 0; mt < 2; mt++) {
      int q = mt*16 + g;
      int col = wid*8 + 2*tg;
      *(float2*)&sL[q*LSTR + col]     = make_float2(acc2[mt][0], acc2[mt][1]);
      *(float2*)&sL[(q+8)*LSTR + col] = make_float2(acc2[mt][2], acc2[mt][3]);
    }
  }
  __syncthreads();

  // ---- bias + scale + softmax: 8 threads per query ----
  {
    const int q = tid >> 3, l8 = tid & 7;
    float* srow = sS + q*SSTR;
    const float* lrow = sL + q*LSTR;
    const int w8 = (w0 + q) >> 3;
    float mx = -1e30f;
    #pragma unroll
    for (int i = 0; i < 32; i++) {
      int j = i*8 + l8;
      float s = (srow[j] + lrow[(j >> 4) - h8 + 15] + lrow[32 + (j & 15) - w8 + 15]) * 0.125f;
      srow[j] = s;
      mx = fmaxf(mx, s);
    }
    mx = fmaxf(mx, __shfl_xor_sync(0xffffffffu, mx, 1));
    mx = fmaxf(mx, __shfl_xor_sync(0xffffffffu, mx, 2));
    mx = fmaxf(mx, __shfl_xor_sync(0xffffffffu, mx, 4));
    float sum = 0.f;
    #pragma unroll
    for (int i = 0; i < 32; i++) {
      int j = i*8 + l8;
      float e2 = __expf(srow[j] - mx);
      srow[j] = e2;
      sum += e2;
    }
    sum += __shfl_xor_sync(0xffffffffu, sum, 1);
    sum += __shfl_xor_sync(0xffffffffu, sum, 2);
    sum += __shfl_xor_sync(0xffffffffu, sum, 4);
    float inv = 1.f / sum;
    #pragma unroll
    for (int i = 0; i < 32; i++) srow[i*8 + l8] *= inv;
  }
  __syncthreads();

  // ---- attn write + P split (into dead K region); V half 0 load (dead Q/R/L) ----
  // 32 queries x 128 pairs = 4096 elements -> 16 iterations of 256 threads
  float* aout = attn_out + ((size_t)(b*NHEADS + head)*NHW + i0)*NSS;
  #pragma unroll 4
  for (int it = 0; it < 16; it++) {
    int e = it*256 + tid;
    int qi = e >> 7, jp = e & 127;
    float2 p2 = *(const float2*)&sS[qi*SSTR + 2*jp];
    *(float2*)&aout[(size_t)qi*NSS + 2*jp] = p2;
    splitpack(p2.x, p2.y, sPb[qi*PPP + jp], sPs[qi*PPP + jp]);
  }
  #pragma unroll
  for (int it = 0; it < 16; it++) {
    int e = it*256 + tid;
    int d = e >> 6, jp = e & 63;
    float2 v2 = *(const float2*)&vp[((size_t)(b*NINNER) + d*NHEADS + head)*NSS + 2*jp];
    splitpack(v2.x, v2.y, sVb[d*VPP + jp], sVs[d*VPP + jp]);
  }
  __syncthreads();

  // ================= AV (two j-halves) =================
  {
    float acc3[2][4];
    #pragma unroll
    for (int j=0;j<2;j++)
      #pragma unroll
      for (int l=0;l<4;l++) acc3[j][l]=0.f;

    #pragma unroll 1
    for (int half = 0; half < 2; half++) {
      if (half == 1) {
        __syncthreads();
        #pragma unroll
        for (int it = 0; it < 16; it++) {
          int e = it*256 + tid;
          int d = e >> 6, jp = e & 63;
          float2 v2 = *(const float2*)&vp[((size_t)(b*NINNER) + d*NHEADS + head)*NSS + 128 + 2*jp];
          splitpack(v2.x, v2.y, sVb[d*VPP + jp], sVs[d*VPP + jp]);
        }
        __syncthreads();
      }
      const int p0 = half*64;
      #pragma unroll 4
      for (int ks = 0; ks < 8; ks++) {
        int k0 = ks*8;
        int q = wm*16 + g;
        uint32_t ab[4], as_[4];
        ab[0]  = sPb[q*PPP + p0 + k0 + tg];
        ab[1]  = sPb[(q+8)*PPP + p0 + k0 + tg];
        ab[2]  = sPb[q*PPP + p0 + k0 + tg + 4];
        ab[3]  = sPb[(q+8)*PPP + p0 + k0 + tg + 4];
        as_[0] = sPs[q*PPP + p0 + k0 + tg];
        as_[1] = sPs[(q+8)*PPP + p0 + k0 + tg];
        as_[2] = sPs[q*PPP + p0 + k0 + tg + 4];
        as_[3] = sPs[(q+8)*PPP + p0 + k0 + tg + 4];
        #pragma unroll
        for (int nt = 0; nt < 2; nt++) {
          int d = wn*16 + nt*8 + g;
          uint32_t bb[2], bs[2];
          bb[0] = sVb[d*VPP + k0 + tg];
          bb[1] = sVb[d*VPP + k0 + tg + 4];
          bs[0] = sVs[d*VPP + k0 + tg];
          bs[1] = sVs[d*VPP + k0 + tg + 4];
          mma16(acc3[nt], ab,  bb);
          mma16(acc3[nt], ab,  bs);
          mma16(acc3[nt], as_, bb);
        }
      }
    }
    // sS is dead (P split done) -> stage output there
    {
      int q = wm*16 + g;
      #pragma unroll
      for (int nt = 0; nt < 2; nt++) {
        int col = wn*16 + nt*8 + 2*tg;
        *(float2*)&sO[q*OSTR + col]     = make_float2(acc3[nt][0], acc3[nt][1]);
        *(float2*)&sO[(q+8)*OSTR + col] = make_float2(acc3[nt][2], acc3[nt][3]);
      }
    }
  }
  __syncthreads();
  #pragma unroll
  for (int l = 0; l < 8; l++) {
    int e = l*256 + tid;
    int d = e >> 5, qi = e & 31;
    av[((size_t)(b*NINNER) + d*NHEADS + head)*NHW + i0 + qi] = sO[qi*OSTR + d];
  }
}

// ======================= launch =======================
extern "C" void kernel_launch(void* const* d_in, const int* in_sizes, int n_in,
                              void* d_out, int out_size) {
  const float* x    = (const float*)d_in[0];
  const float* dw1  = (const float*)d_in[1];
  const float* pw1  = (const float*)d_in[2];
  const float* relw = (const float*)d_in[3];
  const float* relh = (const float*)d_in[4];
  const float* dw2  = (const float*)d_in[5];
  const float* pw2  = (const float*)d_in[6];

  float* out  = (float*)d_out;
  float* attn = out + (size_t)NB*NINNER*NHW;

  float *t1t, *qkvb, *kpb, *vpb, *avb, *t2t;
  cudaGetSymbolAddress((void**)&t1t, g_t1t);
  cudaGetSymbolAddress((void**)&qkvb,g_qkv);
  cudaGetSymbolAddress((void**)&kpb, g_kp);
  cudaGetSymbolAddress((void**)&vpb, g_vp);
  cudaGetSymbolAddress((void**)&avb, g_av);
  cudaGetSymbolAddress((void**)&t2t, g_t2t);

  const int at_smem = 26752*4;   // 107008 B -> 2 CTAs/SM
  cudaFuncSetAttribute(attn_k, cudaFuncAttributeMaxDynamicSharedMemorySize, at_smem);

  dw_t<<<dim3(NHW/32, 8, NB), 256>>>(x, dw1, t1t);
  mm_bf16<<<dim3(NHW/128, 768/128, NB), 256>>>(pw1, t1t, qkvb, 768);
  pool8<<<(2*NB*NINNER*NSS)/256, 256>>>(qkvb, kpb, vpb);
  attn_k<<<dim3(NHW/32, NHEADS, NB), 256, at_smem>>>(qkvb, kpb, vpb, relw, relh,
                                                     attn, avb);
  dw_t<<<dim3(NHW/32, 8, NB), 256>>>(avb, dw2, t2t);
  mm_bf16<<<dim3(NHW/128, 256/128, NB), 256>>>(pw2, t2t, out, 256);
}

// round 12
// speedup vs baseline: 1.1371x; 1.1371x over previous
#include <cuda_runtime.h>
#include <cuda_bf16.h>
#include <math.h>
#include <stdint.h>

#define NB 4
#define NC 256
#define NH 128
#define NW 128
#define NHW (NH*NW)
#define NINNER 256
#define NHEADS 4
#define NDH 64
#define NS 16
#define NSS 256
#define QT 64
#define GK 256

// -------- scratch --------
__device__ float g_t1t[NB*NHW*NC];
__device__ float g_qkv[NB*3*NINNER*NHW];
__device__ float g_kp [NB*NINNER*NSS];
__device__ float g_vp [NB*NINNER*NSS];
__device__ float g_av [NB*NINNER*NHW];
__device__ float g_t2t[NB*NHW*NINNER];

// ---- bf16x3 helpers ----
__device__ __forceinline__ void splitpack(float x0, float x1, uint32_t& b, uint32_t& s) {
  __nv_bfloat162 hb = __floats2bfloat162_rn(x0, x1);
  uint32_t bb = *(uint32_t*)&hb;
  float b0 = __uint_as_float(bb << 16);
  float b1 = __uint_as_float(bb & 0xffff0000u);
  __nv_bfloat162 hs = __floats2bfloat162_rn(x0 - b0, x1 - b1);
  b = bb;
  s = *(uint32_t*)&hs;
}
__device__ __forceinline__ void mma16(float* c, const uint32_t* a, const uint32_t* b) {
  asm volatile("mma.sync.aligned.m16n8k16.row.col.f32.bf16.bf16.f32 "
    "{%0,%1,%2,%3}, {%4,%5,%6,%7}, {%8,%9}, {%0,%1,%2,%3};"
    : "+f"(c[0]), "+f"(c[1]), "+f"(c[2]), "+f"(c[3])
    : "r"(a[0]), "r"(a[1]), "r"(a[2]), "r"(a[3]), "r"(b[0]), "r"(b[1]));
}

// ============== fused depthwise 3x3 (pad 1) + transpose ==============
__global__ void __launch_bounds__(256) dw_t(const float* __restrict__ in,
                                            const float* __restrict__ wt,
                                            float* __restrict__ out) {
  __shared__ float t[32][33];
  int hw0 = blockIdx.x*32, c0 = blockIdx.y*32, b = blockIdx.z;
  int tx = threadIdx.x & 31, ty = threadIdx.x >> 5;
  int x = (hw0 + tx) & (NW-1), y = (hw0 + tx) >> 7;
  #pragma unroll
  for (int r = 0; r < 4; r++) {
    int c = c0 + ty + r*8;
    const float* wp = wt + c*9;
    const float* ip = in + ((size_t)b*256 + c)*NHW;
    float s = 0.f;
    #pragma unroll
    for (int dy = -1; dy <= 1; dy++) {
      int yy = y + dy;
      if ((unsigned)yy >= NH) continue;
      #pragma unroll
      for (int dx = -1; dx <= 1; dx++) {
        int xx = x + dx;
        if ((unsigned)xx >= NW) continue;
        s = fmaf(ip[yy*NW+xx], wp[(dy+1)*3 + dx+1], s);
      }
    }
    t[ty + r*8][tx] = s;
  }
  __syncthreads();
  #pragma unroll
  for (int r = 0; r < 4; r++) {
    int hw = hw0 + ty + r*8;
    out[((size_t)b*NHW + hw)*256 + c0 + tx] = t[tx][ty + r*8];
  }
}

// ======================= bf16x3 mma.sync GEMM =======================
#define GP 20
__global__ void __launch_bounds__(256, 2) mm_bf16(const float* __restrict__ A,
                                                  const float* __restrict__ Bt,
                                                  float* __restrict__ C, int M) {
  __shared__ uint32_t sh[4*128*GP];
  uint32_t* sAb = sh;
  uint32_t* sAs = sh + 2560;
  uint32_t* sBb = sh + 5120;
  uint32_t* sBs = sh + 7680;

  const int tid = threadIdx.x;
  const int wid = tid >> 5, lane = tid & 31;
  const int wm = wid >> 2, wn = wid & 3;
  const int g = lane >> 2, tg = lane & 3;
  const int n0 = blockIdx.x * 128;
  const int m0 = blockIdx.y * 128;
  const int bz = blockIdx.z;

  const float* Arow = A + (size_t)m0*GK;
  const float* Brow = Bt + ((size_t)bz*NHW + n0)*GK;

  float acc[4][4][4];
  #pragma unroll
  for (int i=0;i<4;i++)
    #pragma unroll
    for (int j=0;j<4;j++)
      #pragma unroll
      for (int l=0;l<4;l++) acc[i][j][l] = 0.f;

  for (int kc = 0; kc < GK; kc += 32) {
    #pragma unroll
    for (int i = 0; i < 4; i++) {
      int e = i*256 + tid; int r = e >> 3, c4 = e & 7;
      float4 v = *(const float4*)(Arow + (size_t)r*GK + kc + c4*4);
      uint32_t b0, s0, b1, s1;
      splitpack(v.x, v.y, b0, s0);
      splitpack(v.z, v.w, b1, s1);
      *(uint2*)&sAb[r*GP + c4*2] = make_uint2(b0, b1);
      *(uint2*)&sAs[r*GP + c4*2] = make_uint2(s0, s1);
      float4 w = *(const float4*)(Brow + (size_t)r*GK + kc + c4*4);
      splitpack(w.x, w.y, b0, s0);
      splitpack(w.z, w.w, b1, s1);
      *(uint2*)&sBb[r*GP + c4*2] = make_uint2(b0, b1);
      *(uint2*)&sBs[r*GP + c4*2] = make_uint2(s0, s1);
    }
    __syncthreads();
    #pragma unroll
    for (int ks = 0; ks < 2; ks++) {
      int k0 = ks*8;
      uint32_t bb[4][2], bs[4][2];
      #pragma unroll
      for (int nt = 0; nt < 4; nt++) {
        int n = wn*32 + nt*8 + g;
        bb[nt][0] = sBb[n*GP + k0 + tg];
        bb[nt][1] = sBb[n*GP + k0 + tg + 4];
        bs[nt][0] = sBs[n*GP + k0 + tg];
        bs[nt][1] = sBs[n*GP + k0 + tg + 4];
      }
      #pragma unroll
      for (int mt = 0; mt < 4; mt++) {
        int m = wm*64 + mt*16 + g;
        uint32_t ab[4], as_[4];
        ab[0]  = sAb[m*GP + k0 + tg];
        ab[1]  = sAb[(m+8)*GP + k0 + tg];
        ab[2]  = sAb[m*GP + k0 + tg + 4];
        ab[3]  = sAb[(m+8)*GP + k0 + tg + 4];
        as_[0] = sAs[m*GP + k0 + tg];
        as_[1] = sAs[(m+8)*GP + k0 + tg];
        as_[2] = sAs[m*GP + k0 + tg + 4];
        as_[3] = sAs[(m+8)*GP + k0 + tg + 4];
        #pragma unroll
        for (int nt = 0; nt < 4; nt++) {
          mma16(acc[mt][nt], ab,  bb[nt]);
          mma16(acc[mt][nt], ab,  bs[nt]);
          mma16(acc[mt][nt], as_, bb[nt]);
        }
      }
    }
    __syncthreads();
  }

  float* Cb = C + (size_t)bz*M*NHW;
  #pragma unroll
  for (int mt = 0; mt < 4; mt++) {
    int row = m0 + wm*64 + mt*16 + g;
    #pragma unroll
    for (int nt = 0; nt < 4; nt++) {
      int col = n0 + wn*32 + nt*8 + 2*tg;
      *(float2*)(Cb + (size_t)row*NHW + col) =
          make_float2(acc[mt][nt][0], acc[mt][nt][1]);
      *(float2*)(Cb + (size_t)(row+8)*NHW + col) =
          make_float2(acc[mt][nt][2], acc[mt][nt][3]);
    }
  }
}

// ======================= 8x8 max pool =======================
__global__ void pool8(const float* __restrict__ qkv, float* __restrict__ kp,
                      float* __restrict__ vp) {
  int idx = blockIdx.x*256 + threadIdx.x;
  int which = idx >> 18;
  int r = idx & 262143;
  int ow = r & 15, oh = (r >> 4) & 15;
  int c = (r >> 8) & 255;
  int b = r >> 16;
  const float* ip = qkv + ((size_t)(b*768 + (which ? 512 : 256) + c))*NHW
                    + (oh*8)*NW + ow*8;
  float m = -1e30f;
  #pragma unroll
  for (int i=0;i<8;i++)
    #pragma unroll
    for (int j=0;j<8;j++)
      m = fmaxf(m, ip[i*NW+j]);
  if (which) vp[r] = m; else kp[r] = m;
}

// ======================= fused bf16x3 attention, QT=64, fused softmax =======================
// smem words: sS 16640 | Kb 9216 / Ks 9216 (-> Pb/Ps) | Qb/Qs 2x2304 | Rb/Rs 2x2304
//             | sL 4352 | sM 512 | sInv 64   total 49216 = 196864 B
#define SSTR 260
#define KPP 36
#define QPP 36
#define RPP 36
#define PPP 132
#define VPP 68
#define LSTR 68
#define OSTR 66

__global__ void __launch_bounds__(256) attn_k(
    const float* __restrict__ qkv, const float* __restrict__ kp,
    const float* __restrict__ vp, const float* __restrict__ relw,
    const float* __restrict__ relh, float* __restrict__ attn_out,
    float* __restrict__ av) {
  extern __shared__ float smf[];
  uint32_t* smu = (uint32_t*)smf;
  float*    sS  = smf;                    // 16640
  uint32_t* sKb = smu + 16640;            // 9216
  uint32_t* sKs = smu + 25856;            // 9216
  uint32_t* sQb = smu + 35072;            // 2304
  uint32_t* sQs = smu + 37376;            // 2304
  uint32_t* sRb = smu + 39680;            // 2304
  uint32_t* sRs = smu + 41984;            // 2304
  float*    sL  = smf + 44288;            // 4352
  float*    sM  = smf + 48640;            // 512  (64 x 8 partial maxes)
  float*    sInv= smf + 49152;            // 64
  uint32_t* sPb = sKb;                    // P overlays K
  uint32_t* sPs = sKs;
  uint32_t* sVb = smu + 35072;            // V halves overlay Q+R
  uint32_t* sVs = smu + 39424;
  float*    sO  = smf;                    // out overlays sS

  const int tid = threadIdx.x;
  const int wid = tid >> 5, lane = tid & 31;
  const int g = lane >> 2, tg = lane & 3;
  const int head = blockIdx.y;
  const int b = blockIdx.z;
  const int i0 = blockIdx.x*QT;
  const int hq = i0 >> 7;
  const int w0 = i0 & (NW-1);
  const int h8 = hq >> 3;

  // ---- load Q, split+pack (pairs along d) ----
  #pragma unroll
  for (int l = 0; l < 8; l++) {
    int e = l*256 + tid;
    int dp = e >> 6, qi = e & 63;
    float x0 = qkv[((size_t)(b*768) + (2*dp)*NHEADS + head)*NHW + i0 + qi];
    float x1 = qkv[((size_t)(b*768) + (2*dp+1)*NHEADS + head)*NHW + i0 + qi];
    splitpack(x0, x1, sQb[qi*QPP + dp], sQs[qi*QPP + dp]);
  }
  // ---- rel tables padded to 64 rows: 0..30 relh, 32..62 relw ----
  #pragma unroll
  for (int l = 0; l < 8; l++) {
    int e = l*256 + tid;
    int dp = e >> 6, n = e & 63;
    float x0 = 0.f, x1 = 0.f;
    if (n < 31)                 { x0 = relh[n*64 + 2*dp];      x1 = relh[n*64 + 2*dp + 1]; }
    else if (n >= 32 && n < 63) { x0 = relw[(n-32)*64 + 2*dp]; x1 = relw[(n-32)*64 + 2*dp + 1]; }
    splitpack(x0, x1, sRb[n*RPP + dp], sRs[n*RPP + dp]);
  }
  // ---- load K row j = tid (all 256 keys), split+pack ----
  #pragma unroll 8
  for (int dp = 0; dp < 32; dp++) {
    float x0 = kp[((size_t)(b*NINNER) + (2*dp)*NHEADS + head)*NSS + tid];
    float x1 = kp[((size_t)(b*NINNER) + (2*dp+1)*NHEADS + head)*NSS + tid];
    splitpack(x0, x1, sKb[tid*KPP + dp], sKs[tid*KPP + dp]);
  }
  __syncthreads();

  // ================= QK scores (acc stays in regs) =================
  const int n0w = wid*32;
  float acc[4][4][4];
  #pragma unroll
  for (int i=0;i<4;i++)
    #pragma unroll
    for (int j=0;j<4;j++)
      #pragma unroll
      for (int l=0;l<4;l++) acc[i][j][l]=0.f;
  #pragma unroll
  for (int ks = 0; ks < 4; ks++) {
    int k0 = ks*8;
    uint32_t bb[4][2], bs[4][2];
    #pragma unroll
    for (int nt = 0; nt < 4; nt++) {
      int j = n0w + nt*8 + g;
      bb[nt][0] = sKb[j*KPP + k0 + tg];
      bb[nt][1] = sKb[j*KPP + k0 + tg + 4];
      bs[nt][0] = sKs[j*KPP + k0 + tg];
      bs[nt][1] = sKs[j*KPP + k0 + tg + 4];
    }
    #pragma unroll
    for (int mt = 0; mt < 4; mt++) {
      int q = mt*16 + g;
      uint32_t ab[4], as_[4];
      ab[0]  = sQb[q*QPP + k0 + tg];
      ab[1]  = sQb[(q+8)*QPP + k0 + tg];
      ab[2]  = sQb[q*QPP + k0 + tg + 4];
      ab[3]  = sQb[(q+8)*QPP + k0 + tg + 4];
      as_[0] = sQs[q*QPP + k0 + tg];
      as_[1] = sQs[(q+8)*QPP + k0 + tg];
      as_[2] = sQs[q*QPP + k0 + tg + 4];
      as_[3] = sQs[(q+8)*QPP + k0 + tg + 4];
      #pragma unroll
      for (int nt = 0; nt < 4; nt++) {
        mma16(acc[mt][nt], ab,  bb[nt]);
        mma16(acc[mt][nt], ab,  bs[nt]);
        mma16(acc[mt][nt], as_, bb[nt]);
      }
    }
  }
  // ================= bias logits (64 x 64, warp = 8 cols) =================
  {
    float acc2[4][4];
    #pragma unroll
    for (int i=0;i<4;i++)
      #pragma unroll
      for (int l=0;l<4;l++) acc2[i][l]=0.f;
    #pragma unroll
    for (int ks = 0; ks < 4; ks++) {
      int k0 = ks*8;
      int n = wid*8 + g;
      uint32_t bb[2], bs[2];
      bb[0] = sRb[n*RPP + k0 + tg];
      bb[1] = sRb[n*RPP + k0 + tg + 4];
      bs[0] = sRs[n*RPP + k0 + tg];
      bs[1] = sRs[n*RPP + k0 + tg + 4];
      #pragma unroll
      for (int mt = 0; mt < 4; mt++) {
        int q = mt*16 + g;
        uint32_t ab[4], as_[4];
        ab[0]  = sQb[q*QPP + k0 + tg];
        ab[1]  = sQb[(q+8)*QPP + k0 + tg];
        ab[2]  = sQb[q*QPP + k0 + tg + 4];
        ab[3]  = sQb[(q+8)*QPP + k0 + tg + 4];
        as_[0] = sQs[q*QPP + k0 + tg];
        as_[1] = sQs[(q+8)*QPP + k0 + tg];
        as_[2] = sQs[q*QPP + k0 + tg + 4];
        as_[3] = sQs[(q+8)*QPP + k0 + tg + 4];
        mma16(acc2[mt], ab,  bb);
        mma16(acc2[mt], ab,  bs);
        mma16(acc2[mt], as_, bb);
      }
    }
    #pragma unroll
    for (int mt = 0; mt < 4; mt++) {
      int q = mt*16 + g;
      int col = wid*8 + 2*tg;
      *(float2*)&sL[q*LSTR + col]     = make_float2(acc2[mt][0], acc2[mt][1]);
      *(float2*)&sL[(q+8)*LSTR + col] = make_float2(acc2[mt][2], acc2[mt][3]);
    }
  }
  __syncthreads();   // sL visible to all warps

  // ======= QK epilogue: add bias, scale, store scores, row-max partials =======
  #pragma unroll
  for (int mt = 0; mt < 4; mt++) {
    #pragma unroll
    for (int rr = 0; rr < 2; rr++) {
      int qq = mt*16 + rr*8 + g;
      const float* lrow = sL + qq*LSTR;
      const int w8 = (w0 + qq) >> 3;
      float mxv = -1e30f;
      #pragma unroll
      for (int nt = 0; nt < 4; nt++) {
        int col = n0w + nt*8 + 2*tg;
        float lh  = lrow[(col >> 4) - h8 + 15];
        float lw0 = lrow[32 + (col & 15) - w8 + 15];
        float lw1 = lrow[32 + ((col+1) & 15) - w8 + 15];
        float s0 = (acc[mt][nt][rr*2+0] + lh + lw0) * 0.125f;
        float s1 = (acc[mt][nt][rr*2+1] + lh + lw1) * 0.125f;
        *(float2*)&sS[qq*SSTR + col] = make_float2(s0, s1);
        mxv = fmaxf(mxv, fmaxf(s0, s1));
      }
      mxv = fmaxf(mxv, __shfl_xor_sync(0xffffffffu, mxv, 1));
      mxv = fmaxf(mxv, __shfl_xor_sync(0xffffffffu, mxv, 2));
      if (tg == 0) sM[qq*8 + wid] = mxv;
    }
  }
  __syncthreads();

  // ======= exp + sum in one pass (4 threads/query); V half 0 load =======
  {
    const int q = tid >> 2, l4 = tid & 3;
    float* srow = sS + q*SSTR;
    float mx = sM[q*8];
    #pragma unroll
    for (int w = 1; w < 8; w++) mx = fmaxf(mx, sM[q*8 + w]);
    float sum = 0.f;
    #pragma unroll
    for (int i = 0; i < 64; i++) {
      int j = i*4 + l4;
      float e2 = __expf(srow[j] - mx);
      srow[j] = e2;
      sum += e2;
    }
    sum += __shfl_xor_sync(0xffffffffu, sum, 1);
    sum += __shfl_xor_sync(0xffffffffu, sum, 2);
    if (l4 == 0) sInv[q] = 1.f / sum;
  }
  #pragma unroll
  for (int it = 0; it < 16; it++) {
    int e = it*256 + tid;
    int d = e >> 6, jp = e & 63;
    float2 v2 = *(const float2*)&vp[((size_t)(b*NINNER) + d*NHEADS + head)*NSS + 2*jp];
    splitpack(v2.x, v2.y, sVb[d*VPP + jp], sVs[d*VPP + jp]);
  }
  __syncthreads();

  // ======= attn write (normalized) + P split into dead K region =======
  float* aout = attn_out + ((size_t)(b*NHEADS + head)*NHW + i0)*NSS;
  #pragma unroll 4
  for (int it = 0; it < 32; it++) {
    int e = it*256 + tid;
    int qi = e >> 7, jp = e & 127;
    float inv = sInv[qi];
    float2 p2 = *(const float2*)&sS[qi*SSTR + 2*jp];
    p2.x *= inv; p2.y *= inv;
    *(float2*)&aout[(size_t)qi*NSS + 2*jp] = p2;
    splitpack(p2.x, p2.y, sPb[qi*PPP + jp], sPs[qi*PPP + jp]);
  }
  __syncthreads();

  // ================= AV (two j-halves) =================
  {
    const int wm = wid >> 2, wn = wid & 3;   // 2 x 4
    float acc3[2][2][4];
    #pragma unroll
    for (int i=0;i<2;i++)
      #pragma unroll
      for (int j=0;j<2;j++)
        #pragma unroll
        for (int l=0;l<4;l++) acc3[i][j][l]=0.f;

    #pragma unroll 1
    for (int half = 0; half < 2; half++) {
      if (half == 1) {
        __syncthreads();
        #pragma unroll
        for (int it = 0; it < 16; it++) {
          int e = it*256 + tid;
          int d = e >> 6, jp = e & 63;
          float2 v2 = *(const float2*)&vp[((size_t)(b*NINNER) + d*NHEADS + head)*NSS + 128 + 2*jp];
          splitpack(v2.x, v2.y, sVb[d*VPP + jp], sVs[d*VPP + jp]);
        }
        __syncthreads();
      }
      const int p0 = half*64;
      #pragma unroll 4
      for (int ks = 0; ks < 8; ks++) {
        int k0 = ks*8;
        uint32_t ab[2][4], as_[2][4];
        #pragma unroll
        for (int mt = 0; mt < 2; mt++) {
          int q = wm*32 + mt*16 + g;
          ab[mt][0]  = sPb[q*PPP + p0 + k0 + tg];
          ab[mt][1]  = sPb[(q+8)*PPP + p0 + k0 + tg];
          ab[mt][2]  = sPb[q*PPP + p0 + k0 + tg + 4];
          ab[mt][3]  = sPb[(q+8)*PPP + p0 + k0 + tg + 4];
          as_[mt][0] = sPs[q*PPP + p0 + k0 + tg];
          as_[mt][1] = sPs[(q+8)*PPP + p0 + k0 + tg];
          as_[mt][2] = sPs[q*PPP + p0 + k0 + tg + 4];
          as_[mt][3] = sPs[(q+8)*PPP + p0 + k0 + tg + 4];
        }
        uint32_t bb[2][2], bs[2][2];
        #pragma unroll
        for (int nt = 0; nt < 2; nt++) {
          int d = wn*16 + nt*8 + g;
          bb[nt][0] = sVb[d*VPP + k0 + tg];
          bb[nt][1] = sVb[d*VPP + k0 + tg + 4];
          bs[nt][0] = sVs[d*VPP + k0 + tg];
          bs[nt][1] = sVs[d*VPP + k0 + tg + 4];
        }
        #pragma unroll
        for (int mt = 0; mt < 2; mt++)
          #pragma unroll
          for (int nt = 0; nt < 2; nt++) {
            mma16(acc3[mt][nt], ab[mt],  bb[nt]);
            mma16(acc3[mt][nt], ab[mt],  bs[nt]);
            mma16(acc3[mt][nt], as_[mt], bb[nt]);
          }
      }
    }
    #pragma unroll
    for (int mt = 0; mt < 2; mt++) {
      int q = wm*32 + mt*16 + g;
      #pragma unroll
      for (int nt = 0; nt < 2; nt++) {
        int col = wn*16 + nt*8 + 2*tg;
        *(float2*)&sO[q*OSTR + col]     = make_float2(acc3[mt][nt][0], acc3[mt][nt][1]);
        *(float2*)&sO[(q+8)*OSTR + col] = make_float2(acc3[mt][nt][2], acc3[mt][nt][3]);
      }
    }
  }
  __syncthreads();
  #pragma unroll
  for (int l = 0; l < 16; l++) {
    int e = l*256 + tid;
    int d = e >> 6, qi = e & 63;
    av[((size_t)(b*NINNER) + d*NHEADS + head)*NHW + i0 + qi] = sO[qi*OSTR + d];
  }
}

// ======================= launch =======================
extern "C" void kernel_launch(void* const* d_in, const int* in_sizes, int n_in,
                              void* d_out, int out_size) {
  const float* x    = (const float*)d_in[0];
  const float* dw1  = (const float*)d_in[1];
  const float* pw1  = (const float*)d_in[2];
  const float* relw = (const float*)d_in[3];
  const float* relh = (const float*)d_in[4];
  const float* dw2  = (const float*)d_in[5];
  const float* pw2  = (const float*)d_in[6];

  float* out  = (float*)d_out;
  float* attn = out + (size_t)NB*NINNER*NHW;

  float *t1t, *qkvb, *kpb, *vpb, *avb, *t2t;
  cudaGetSymbolAddress((void**)&t1t, g_t1t);
  cudaGetSymbolAddress((void**)&qkvb,g_qkv);
  cudaGetSymbolAddress((void**)&kpb, g_kp);
  cudaGetSymbolAddress((void**)&vpb, g_vp);
  cudaGetSymbolAddress((void**)&avb, g_av);
  cudaGetSymbolAddress((void**)&t2t, g_t2t);

  const int at_smem = 49216*4;   // 196864 B
  cudaFuncSetAttribute(attn_k, cudaFuncAttributeMaxDynamicSharedMemorySize, at_smem);

  dw_t<<<dim3(NHW/32, 8, NB), 256>>>(x, dw1, t1t);
  mm_bf16<<<dim3(NHW/128, 768/128, NB), 256>>>(pw1, t1t, qkvb, 768);
  pool8<<<(2*NB*NINNER*NSS)/256, 256>>>(qkvb, kpb, vpb);
  attn_k<<<dim3(NHW/QT, NHEADS, NB), 256, at_smem>>>(qkvb, kpb, vpb, relw, relh,
                                                     attn, avb);
  dw_t<<<dim3(NHW/32, 8, NB), 256>>>(avb, dw2, t2t);
  mm_bf16<<<dim3(NHW/128, 256/128, NB), 256>>>(pw2, t2t, out, 256);
}